// round 5
// baseline (speedup 1.0000x reference)
#include <cuda_runtime.h>
#include <cuda_fp16.h>
#include <cstdint>

// ---------------- problem constants ----------------
#define CIN   256
#define KOUT  256
#define HH    56
#define WW    56
#define NPF   2304           // 256*3*3 per output filter
#define PH    58
#define PW    58
#define NIMG  32
#define PIX   (HH*WW)        // 3136
#define MTOT  (NIMG*PIX)     // 100352

// ---------------- GEMM tiling ----------------
#define MT    128            // CTA M tile
#define NT    128            // CTA N tile
#define KC    32             // K chunk (halfs)
#define NCH   72             // 9 taps * 8 chunks of 32 channels
#define NS    4              // pipeline stages

// smem stage: A(128 rows x 80B) + B(128 rows x 80B); 80B stride -> conflict-free ldsm
#define ROWB  80
#define ASTG  (128*ROWB)     // 10240
#define STG   (2*ASTG)       // 20480
#define SMDYN (NS*STG)       // 81920

// ---------------- device scratch ----------------
__device__ __half g_b[9 * KOUT * CIN];                   // [rs][k][c], +-1
__device__ float  g_alpha[KOUT];
__device__ __half g_xpad[(size_t)NIMG * PH * PW * CIN];  // [n][hp][wp][c]

// ---------------- ptx helpers (family-portable only) ----------------
__device__ __forceinline__ void cp16(uint32_t dst, const void* src) {
    asm volatile("cp.async.cg.shared.global [%0], [%1], 16;"
                 :: "r"(dst), "l"(__cvta_generic_to_global(src)) : "memory");
}
#define CP_COMMIT()  asm volatile("cp.async.commit_group;" ::: "memory")
#define CP_WAIT(N)   asm volatile("cp.async.wait_group %0;" :: "n"(N) : "memory")

#define LDSM4(R, addr)                                                        \
    asm volatile("ldmatrix.sync.aligned.m8n8.x4.shared.b16 {%0,%1,%2,%3}, [%4];" \
                 : "=r"((R)[0]), "=r"((R)[1]), "=r"((R)[2]), "=r"((R)[3])     \
                 : "r"(addr))

#define MMA16816(D, A, B0, B1)                                                \
    asm volatile("mma.sync.aligned.m16n8k16.row.col.f32.f16.f16.f32 "         \
                 "{%0,%1,%2,%3}, {%4,%5,%6,%7}, {%8,%9}, {%0,%1,%2,%3};"      \
                 : "+f"((D)[0]), "+f"((D)[1]), "+f"((D)[2]), "+f"((D)[3])     \
                 : "r"((A)[0]), "r"((A)[1]), "r"((A)[2]), "r"((A)[3]),        \
                   "r"(B0), "r"(B1))

// ---------------------------------------------------------------------------
// K0: ternarize. One block per output filter o.
// ---------------------------------------------------------------------------
__global__ void ternarize_kernel(const float* __restrict__ w) {
    const int o = blockIdx.x;
    const int tid = threadIdx.x;
    const float* wo = w + (size_t)o * NPF;
    __shared__ float red[256];

    float s = 0.f;
    for (int i = tid; i < NPF; i += 256) s += fabsf(wo[i]);
    red[tid] = s; __syncthreads();
    for (int st = 128; st > 0; st >>= 1) {
        if (tid < st) red[tid] += red[tid + st];
        __syncthreads();
    }
    const float delta = (0.7f / (float)NPF) * red[0];
    __syncthreads();

    float cnt = 0.f, asum = 0.f;
    for (int i = tid; i < NPF; i += 256) {
        float a = fabsf(wo[i]);
        if (a > delta) { cnt += 1.f; asum += a; }
    }
    red[tid] = cnt; __syncthreads();
    for (int st = 128; st > 0; st >>= 1) {
        if (tid < st) red[tid] += red[tid + st];
        __syncthreads();
    }
    const float cnt_tot = red[0];
    __syncthreads();
    red[tid] = asum; __syncthreads();
    for (int st = 128; st > 0; st >>= 1) {
        if (tid < st) red[tid] += red[tid + st];
        __syncthreads();
    }
    const float alpha = red[0] / cnt_tot;

    for (int i = tid; i < NPF; i += 256) {
        float v = wo[i];
        float t = (v > delta) ? 1.f : ((v < -delta) ? -1.f : 0.f);
        int c = i / 9, rs = i % 9;
        g_b[((size_t)rs * KOUT + o) * CIN + c] = __float2half_rn(t);
    }
    if (tid == 0) g_alpha[o] = alpha;
}

// ---------------------------------------------------------------------------
// K1: pad + NCHW->NHWC transpose + fp16 convert (border rows write zeros).
// grid (58 hp, 4 c-chunks, 32 n), 256 threads
// ---------------------------------------------------------------------------
__global__ void pad_transpose_kernel(const float* __restrict__ x) {
    __shared__ float s[64][57];
    const int hp = blockIdx.x, c0 = blockIdx.y * 64, n = blockIdx.z;
    __half* dst = g_xpad + ((size_t)(n * PH + hp) * PW) * CIN + c0;

    if (hp == 0 || hp == PH - 1) {
        // zero border row: 58 wp x 64 halfs = 464 uint4
        for (int idx = threadIdx.x; idx < PW * 8; idx += 256) {
            int wp = idx >> 3, u = idx & 7;
            ((uint4*)(dst + (size_t)wp * CIN))[u] = make_uint4(0u, 0u, 0u, 0u);
        }
        return;
    }

    const int h = hp - 1;
    const float* xp = x + ((size_t)(n * CIN + c0) * HH + h) * WW;
    for (int idx = threadIdx.x; idx < 64 * WW; idx += 256) {
        int ci = idx / WW, w = idx - ci * WW;
        s[ci][w] = xp[(size_t)ci * PIX + w];
    }
    __syncthreads();

    for (int idx = threadIdx.x; idx < PW * 64; idx += 256) {
        int wp = idx / 64, ci = idx - wp * 64;
        float v = (wp >= 1 && wp <= WW) ? s[ci][wp - 1] : 0.f;
        dst[(size_t)wp * CIN + ci] = __float2half_rn(v);
    }
}

// ---------------------------------------------------------------------------
// K2: implicit-GEMM conv via mma.sync m16n8k16.
// Grid (784, 2): CTA = 128 pixels x 128 out channels.
// 4 warps, warp tile 64x64 (4 MMA per ldmatrix.x4), KC=32, NS=4 pipeline.
// ---------------------------------------------------------------------------
__global__ void __launch_bounds__(128)
conv_mma_kernel(const float* __restrict__ bias_g, float* __restrict__ out) {
    extern __shared__ __align__(128) char smem[];
    const uint32_t sb = (uint32_t)__cvta_generic_to_shared(smem);

    const int tid = threadIdx.x;
    const int lane = tid & 31;
    const int wid = tid >> 5;
    const int warp_m = wid >> 1;   // 0..1
    const int warp_n = wid & 1;    // 0..1

    const int p0 = blockIdx.x * MT;
    const int n0 = blockIdx.y * NT;

    __shared__ float s_alpha[128], s_bias[128];
    s_alpha[tid] = g_alpha[n0 + tid];
    s_bias[tid]  = bias_g[n0 + tid];

    // ---- per-thread cp.async source/dest precompute ----
    // 128 threads; each: 4 A rows + 4 B rows (rows 0..127, 16B seg each)
    const int seg  = tid & 3;            // 16B segment of 64B row
    const int arow = tid >> 2;           // 0..31
    const __half* a_g[4];
    #pragma unroll
    for (int q = 0; q < 4; q++) {
        int row = arow + q * 32;
        int p = p0 + row;
        int n = p / PIX; int rem = p - n * PIX;
        int h = rem / WW; int w = rem - h * WW;
        a_g[q] = g_xpad + ((size_t)((n * PH + h) * PW + w)) * CIN + seg * 8;
    }
    const __half* b_g[4];
    #pragma unroll
    for (int q = 0; q < 4; q++)
        b_g[q] = g_b + (size_t)(n0 + arow + q * 32) * CIN + seg * 8;
    uint32_t s_off[4];
    #pragma unroll
    for (int q = 0; q < 4; q++)
        s_off[q] = (uint32_t)((arow + q * 32) * ROWB + seg * 16);

    // ---- ldmatrix address precompute ----
    uint32_t a_lm[4];
    {
        int rr = lane & 15;
        int ch = (lane >> 4) * 8;
        #pragma unroll
        for (int i = 0; i < 4; i++)
            a_lm[i] = (uint32_t)((warp_m * 64 + i * 16 + rr) * ROWB + ch * 2);
    }
    uint32_t b_lm[4];
    {
        int nn = (lane & 7) + ((lane & 16) >> 1);
        int kk0 = lane & 8;
        #pragma unroll
        for (int j = 0; j < 4; j++)
            b_lm[j] = (uint32_t)((warp_n * 64 + j * 16 + nn) * ROWB + kk0 * 2);
    }

    float acc[4][8][4];
    #pragma unroll
    for (int i = 0; i < 4; i++)
        #pragma unroll
        for (int j = 0; j < 8; j++)
            #pragma unroll
            for (int r = 0; r < 4; r++) acc[i][j][r] = 0.f;

    auto fill = [&](int st, int ch) {
        int rs = ch >> 3, cc = ch & 7;
        int r = rs / 3, s = rs - r * 3;
        size_t aoff = (size_t)((r * PW + s) * CIN + cc * KC);
        size_t boff = (size_t)rs * (KOUT * CIN) + cc * KC;
        uint32_t ab = sb + st * STG;
        uint32_t bb = ab + ASTG;
        #pragma unroll
        for (int q = 0; q < 4; q++) cp16(ab + s_off[q], a_g[q] + aoff);
        #pragma unroll
        for (int q = 0; q < 4; q++) cp16(bb + s_off[q], b_g[q] + boff);
        CP_COMMIT();
    };

    // ---- pipelined mainloop ----
    fill(0, 0); fill(1, 1); fill(2, 2);

    int st = 0;
    for (int ch = 0; ch < NCH; ch++) {
        CP_WAIT(2);
        __syncthreads();
        if (ch + 3 < NCH) fill((st + 3) & (NS - 1), ch + 3);
        else              CP_COMMIT();

        uint32_t ab = sb + st * STG;
        uint32_t bb = ab + ASTG;
        #pragma unroll
        for (int kk = 0; kk < 2; kk++) {
            uint32_t a[4][4], b[4][4];
            #pragma unroll
            for (int i = 0; i < 4; i++) LDSM4(a[i], ab + a_lm[i] + kk * 32);
            #pragma unroll
            for (int j = 0; j < 4; j++) LDSM4(b[j], bb + b_lm[j] + kk * 32);
            #pragma unroll
            for (int i = 0; i < 4; i++)
                #pragma unroll
                for (int j = 0; j < 8; j++)
                    MMA16816(acc[i][j], a[i],
                             b[j >> 1][(j & 1) * 2],
                             b[j >> 1][(j & 1) * 2 + 1]);
        }
        st = (st + 1) & (NS - 1);
    }
    CP_WAIT(0);
    __syncthreads();

    // ---- epilogue: stage through smem, out = alpha*acc + bias ----
    float* stile = (float*)smem;   // [128][65]
    int p = p0 + tid;
    int nimg = p / PIX; int hw = p - nimg * PIX;

    #pragma unroll
    for (int phase = 0; phase < 2; phase++) {
        #pragma unroll
        for (int i = 0; i < 4; i++)
            #pragma unroll
            for (int j = 0; j < 8; j++) {
                int nl = warp_n * 64 + j * 8 + (lane & 3) * 2;
                if ((nl >> 6) == phase) {
                    int no = nl & 63;
                    int m0 = warp_m * 64 + i * 16 + (lane >> 2);
                    stile[m0 * 65 + no]           = acc[i][j][0];
                    stile[m0 * 65 + no + 1]       = acc[i][j][1];
                    stile[(m0 + 8) * 65 + no]     = acc[i][j][2];
                    stile[(m0 + 8) * 65 + no + 1] = acc[i][j][3];
                }
            }
        __syncthreads();

        float* ob = out + ((size_t)nimg * KOUT + n0 + phase * 64) * PIX + hw;
        #pragma unroll
        for (int k = 0; k < 64; k++) {
            int kg = phase * 64 + k;
            ob[(size_t)k * PIX] =
                fmaf(s_alpha[kg], stile[tid * 65 + k], s_bias[kg]);
        }
        __syncthreads();
    }
}

// ---------------------------------------------------------------------------
extern "C" void kernel_launch(void* const* d_in, const int* in_sizes, int n_in,
                              void* d_out, int out_size) {
    const float* x      = (const float*)d_in[0];
    const float* weight = (const float*)d_in[1];
    const float* bias   = (const float*)d_in[2];
    float* out          = (float*)d_out;

    cudaFuncSetAttribute(conv_mma_kernel,
                         cudaFuncAttributeMaxDynamicSharedMemorySize, SMDYN);

    ternarize_kernel<<<KOUT, 256>>>(weight);
    pad_transpose_kernel<<<dim3(PH, 4, NIMG), 256>>>(x);
    conv_mma_kernel<<<dim3(MTOT / MT, KOUT / NT), 128, SMDYN>>>(bias, out);
}

// round 6
// speedup vs baseline: 1.1011x; 1.1011x over previous
#include <cuda_runtime.h>
#include <cuda_fp16.h>
#include <cstdint>

// ---------------- problem constants ----------------
#define CIN   256
#define KOUT  256
#define HH    56
#define WW    56
#define NPF   2304           // 256*3*3 per output filter
#define PH    58
#define PW    58
#define NIMG  32
#define PIX   (HH*WW)        // 3136
#define MTOT  (NIMG*PIX)     // 100352

// ---------------- GEMM tiling ----------------
#define MT    128            // CTA M tile
#define NT    128            // CTA N tile
#define KC    32             // K chunk (halfs)
#define NCH   72             // 9 taps * 8 chunks of 32 channels
#define NS    4              // pipeline stages

// smem stage: A(128 rows x 80B) + B(128 rows x 80B); 80B stride -> conflict-free ldsm
#define ROWB  80
#define ASTG  (128*ROWB)     // 10240
#define STG   (2*ASTG)       // 20480
#define SMDYN (NS*STG)       // 81920

// ---------------- device scratch ----------------
__device__ __half g_b[9 * KOUT * CIN];                   // [rs][k][c], +-1
__device__ float  g_alpha[KOUT];
__device__ __half g_xpad[(size_t)NIMG * PH * PW * CIN];  // [n][hp][wp][c]

// ---------------- ptx helpers (family-portable only) ----------------
__device__ __forceinline__ void cp16(uint32_t dst, const void* src) {
    asm volatile("cp.async.cg.shared.global [%0], [%1], 16;"
                 :: "r"(dst), "l"(__cvta_generic_to_global(src)) : "memory");
}
#define CP_COMMIT()  asm volatile("cp.async.commit_group;" ::: "memory")
#define CP_WAIT(N)   asm volatile("cp.async.wait_group %0;" :: "n"(N) : "memory")

#define LDSM4(R, addr)                                                        \
    asm volatile("ldmatrix.sync.aligned.m8n8.x4.shared.b16 {%0,%1,%2,%3}, [%4];" \
                 : "=r"((R)[0]), "=r"((R)[1]), "=r"((R)[2]), "=r"((R)[3])     \
                 : "r"(addr))

#define MMA16816(D, A, B0, B1)                                                \
    asm volatile("mma.sync.aligned.m16n8k16.row.col.f32.f16.f16.f32 "         \
                 "{%0,%1,%2,%3}, {%4,%5,%6,%7}, {%8,%9}, {%0,%1,%2,%3};"      \
                 : "+f"((D)[0]), "+f"((D)[1]), "+f"((D)[2]), "+f"((D)[3])     \
                 : "r"((A)[0]), "r"((A)[1]), "r"((A)[2]), "r"((A)[3]),        \
                   "r"(B0), "r"(B1))

// ---------------------------------------------------------------------------
// K0: ternarize (float4 + warp shuffle reductions). One block per filter.
// ---------------------------------------------------------------------------
__global__ void ternarize_kernel(const float* __restrict__ w) {
    const int o = blockIdx.x;
    const int tid = threadIdx.x;
    const int lane = tid & 31;
    const int wrp = tid >> 5;
    const float4* wo4 = (const float4*)(w + (size_t)o * NPF);  // 576 float4
    __shared__ float red[8];
    __shared__ float s_delta, s_alpha_sh;

    // pass 1: sum |w|
    float s = 0.f;
    for (int i = tid; i < NPF / 4; i += 256) {
        float4 v = wo4[i];
        s += fabsf(v.x) + fabsf(v.y) + fabsf(v.z) + fabsf(v.w);
    }
    #pragma unroll
    for (int d = 16; d > 0; d >>= 1) s += __shfl_xor_sync(~0u, s, d);
    if (lane == 0) red[wrp] = s;
    __syncthreads();
    if (tid == 0) {
        float t = 0.f;
        #pragma unroll
        for (int i = 0; i < 8; i++) t += red[i];
        s_delta = (0.7f / (float)NPF) * t;
    }
    __syncthreads();
    const float delta = s_delta;

    // pass 2: count + masked abs-sum (pack count into low bits trick avoided;
    // two shuffles)
    float cnt = 0.f, asum = 0.f;
    for (int i = tid; i < NPF / 4; i += 256) {
        float4 v = wo4[i];
        float a;
        a = fabsf(v.x); if (a > delta) { cnt += 1.f; asum += a; }
        a = fabsf(v.y); if (a > delta) { cnt += 1.f; asum += a; }
        a = fabsf(v.z); if (a > delta) { cnt += 1.f; asum += a; }
        a = fabsf(v.w); if (a > delta) { cnt += 1.f; asum += a; }
    }
    #pragma unroll
    for (int d = 16; d > 0; d >>= 1) {
        cnt  += __shfl_xor_sync(~0u, cnt, d);
        asum += __shfl_xor_sync(~0u, asum, d);
    }
    if (lane == 0) red[wrp] = cnt;
    __syncthreads();
    float cnt_tot = 0.f;
    if (tid == 0) {
        #pragma unroll
        for (int i = 0; i < 8; i++) cnt_tot += red[i];
        red[0] = cnt_tot;
    }
    __syncthreads();
    cnt_tot = red[0];
    __syncthreads();
    if (lane == 0) red[wrp] = asum;
    __syncthreads();
    if (tid == 0) {
        float t = 0.f;
        #pragma unroll
        for (int i = 0; i < 8; i++) t += red[i];
        s_alpha_sh = t / cnt_tot;
        g_alpha[o] = s_alpha_sh;
    }
    __syncthreads();

    // pass 3: write ternary +-1 fp16, transposed [rs][k][c]
    const float* wo = w + (size_t)o * NPF;
    for (int i = tid; i < NPF; i += 256) {
        float v = wo[i];
        float t = (v > delta) ? 1.f : ((v < -delta) ? -1.f : 0.f);
        int c = i / 9, rs = i % 9;
        g_b[((size_t)rs * KOUT + o) * CIN + c] = __float2half_rn(t);
    }
}

// ---------------------------------------------------------------------------
// K1: pad + NCHW->NHWC transpose + fp16 convert (border rows write zeros).
// grid (58 hp, 4 c-chunks, 32 n), 256 threads
// ---------------------------------------------------------------------------
__global__ void pad_transpose_kernel(const float* __restrict__ x) {
    __shared__ float s[64][57];
    const int hp = blockIdx.x, c0 = blockIdx.y * 64, n = blockIdx.z;
    __half* dst = g_xpad + ((size_t)(n * PH + hp) * PW) * CIN + c0;

    if (hp == 0 || hp == PH - 1) {
        for (int idx = threadIdx.x; idx < PW * 8; idx += 256) {
            int wp = idx >> 3, u = idx & 7;
            ((uint4*)(dst + (size_t)wp * CIN))[u] = make_uint4(0u, 0u, 0u, 0u);
        }
        return;
    }

    const int h = hp - 1;
    const float* xp = x + ((size_t)(n * CIN + c0) * HH + h) * WW;
    for (int idx = threadIdx.x; idx < 64 * WW; idx += 256) {
        int ci = idx / WW, w = idx - ci * WW;
        s[ci][w] = xp[(size_t)ci * PIX + w];
    }
    __syncthreads();

    for (int idx = threadIdx.x; idx < PW * 64; idx += 256) {
        int wp = idx / 64, ci = idx - wp * 64;
        float v = (wp >= 1 && wp <= WW) ? s[ci][wp - 1] : 0.f;
        dst[(size_t)wp * CIN + ci] = __float2half_rn(v);
    }
}

// ---------------------------------------------------------------------------
// K2: implicit-GEMM conv via mma.sync m16n8k16.
// Grid (784, 2): CTA = 128 pixels x 128 out channels. 8 warps, warp 64x32.
// NS=4 pipeline, prefetch distance 3.
// ---------------------------------------------------------------------------
__global__ void __launch_bounds__(256, 2)
conv_mma_kernel(const float* __restrict__ bias_g, float* __restrict__ out) {
    extern __shared__ __align__(128) char smem[];
    const uint32_t sb = (uint32_t)__cvta_generic_to_shared(smem);

    const int tid = threadIdx.x;
    const int lane = tid & 31;
    const int wid = tid >> 5;
    const int warp_m = wid >> 2;   // 0..1
    const int warp_n = wid & 3;    // 0..3

    const int p0 = blockIdx.x * MT;
    const int n0 = blockIdx.y * NT;

    __shared__ float s_alpha[128], s_bias[128];
    if (tid < 128) s_alpha[tid] = g_alpha[n0 + tid];
    else           s_bias[tid - 128] = bias_g[n0 + tid - 128];

    // ---- per-thread cp.async source/dest precompute ----
    const int seg = tid & 3;               // 16B segment of 64B row
    const int arow = tid >> 2;             // 0..63
    const __half* a_g[2];
    #pragma unroll
    for (int q = 0; q < 2; q++) {
        int row = arow + q * 64;
        int p = p0 + row;
        int n = p / PIX; int rem = p - n * PIX;
        int h = rem / WW; int w = rem - h * WW;
        a_g[q] = g_xpad + ((size_t)((n * PH + h) * PW + w)) * CIN + seg * 8;
    }
    const __half* b_g[2];
    #pragma unroll
    for (int q = 0; q < 2; q++)
        b_g[q] = g_b + (size_t)(n0 + arow + q * 64) * CIN + seg * 8;
    const uint32_t s_off0 = (uint32_t)(arow * ROWB + seg * 16);
    const uint32_t s_off1 = s_off0 + 64 * ROWB;

    // ---- ldmatrix address precompute ----
    uint32_t a_lm[4];
    {
        int rr = lane & 15;
        int ch = (lane >> 4) * 8;
        #pragma unroll
        for (int i = 0; i < 4; i++)
            a_lm[i] = (uint32_t)((warp_m * 64 + i * 16 + rr) * ROWB + ch * 2);
    }
    uint32_t b_lm[2];
    {
        int nn = (lane & 7) + ((lane & 16) >> 1);
        int kk0 = lane & 8;
        #pragma unroll
        for (int j = 0; j < 2; j++)
            b_lm[j] = (uint32_t)((warp_n * 32 + j * 16 + nn) * ROWB + kk0 * 2);
    }

    float acc[4][4][4];
    #pragma unroll
    for (int i = 0; i < 4; i++)
        #pragma unroll
        for (int j = 0; j < 4; j++)
            #pragma unroll
            for (int r = 0; r < 4; r++) acc[i][j][r] = 0.f;

    auto fill = [&](int st, int ch) {
        int rs = ch >> 3, cc = ch & 7;
        int r = rs / 3, s = rs - r * 3;
        size_t aoff = (size_t)((r * PW + s) * CIN + cc * KC);
        size_t boff = (size_t)rs * (KOUT * CIN) + cc * KC;
        uint32_t ab = sb + st * STG;
        uint32_t bb = ab + ASTG;
        cp16(ab + s_off0, a_g[0] + aoff);
        cp16(ab + s_off1, a_g[1] + aoff);
        cp16(bb + s_off0, b_g[0] + boff);
        cp16(bb + s_off1, b_g[1] + boff);
        CP_COMMIT();
    };

    // ---- pipelined mainloop: 3 stages in flight ----
    fill(0, 0); fill(1, 1); fill(2, 2);

    int st = 0;
    for (int ch = 0; ch < NCH; ch++) {
        CP_WAIT(2);
        __syncthreads();
        if (ch + 3 < NCH) fill((st + 3) & (NS - 1), ch + 3);
        else              CP_COMMIT();

        uint32_t ab = sb + st * STG;
        uint32_t bb = ab + ASTG;
        #pragma unroll
        for (int kk = 0; kk < 2; kk++) {
            uint32_t a[4][4], b[2][4];
            #pragma unroll
            for (int i = 0; i < 4; i++) LDSM4(a[i], ab + a_lm[i] + kk * 32);
            #pragma unroll
            for (int j = 0; j < 2; j++) LDSM4(b[j], bb + b_lm[j] + kk * 32);
            #pragma unroll
            for (int i = 0; i < 4; i++)
                #pragma unroll
                for (int j2 = 0; j2 < 4; j2++)
                    MMA16816(acc[i][j2], a[i],
                             b[j2 >> 1][(j2 & 1) * 2],
                             b[j2 >> 1][(j2 & 1) * 2 + 1]);
        }
        st = (st + 1) & (NS - 1);
    }
    CP_WAIT(0);
    __syncthreads();

    // ---- epilogue: stage through smem, out = alpha*acc + bias ----
    float* stile = (float*)smem;   // [128][65]
    const int m_ep = tid & 127;
    const int kb = tid >> 7;       // 0/1
    int p = p0 + m_ep;
    int nimg = p / PIX; int hw = p - nimg * PIX;

    #pragma unroll
    for (int phase = 0; phase < 2; phase++) {
        #pragma unroll
        for (int i = 0; i < 4; i++)
            #pragma unroll
            for (int j2 = 0; j2 < 4; j2++) {
                int nl = warp_n * 32 + j2 * 8 + (lane & 3) * 2;
                if ((nl >> 6) == phase) {
                    int no = nl & 63;
                    int m0 = warp_m * 64 + i * 16 + (lane >> 2);
                    stile[m0 * 65 + no]           = acc[i][j2][0];
                    stile[m0 * 65 + no + 1]       = acc[i][j2][1];
                    stile[(m0 + 8) * 65 + no]     = acc[i][j2][2];
                    stile[(m0 + 8) * 65 + no + 1] = acc[i][j2][3];
                }
            }
        __syncthreads();

        float* ob = out + ((size_t)nimg * KOUT + n0 + phase * 64) * PIX + hw;
        #pragma unroll
        for (int it = 0; it < 32; it++) {
            int k = it * 2 + kb;
            int kg = phase * 64 + k;
            float v = stile[m_ep * 65 + k];
            ob[(size_t)k * PIX] = fmaf(s_alpha[kg], v, s_bias[kg]);
        }
        __syncthreads();
    }
}

// ---------------------------------------------------------------------------
extern "C" void kernel_launch(void* const* d_in, const int* in_sizes, int n_in,
                              void* d_out, int out_size) {
    const float* x      = (const float*)d_in[0];
    const float* weight = (const float*)d_in[1];
    const float* bias   = (const float*)d_in[2];
    float* out          = (float*)d_out;

    cudaFuncSetAttribute(conv_mma_kernel,
                         cudaFuncAttributeMaxDynamicSharedMemorySize, SMDYN);

    ternarize_kernel<<<KOUT, 256>>>(weight);
    pad_transpose_kernel<<<dim3(PH, 4, NIMG), 256>>>(x);
    conv_mma_kernel<<<dim3(MTOT / MT, KOUT / NT), 256, SMDYN>>>(bias, out);
}